// round 3
// baseline (speedup 1.0000x reference)
#include <cuda_runtime.h>
#include <cuda_bf16.h>
#include <cstdint>

// ---------------------------------------------------------------------------
// VectorQuantize: z [32768,512] f32, codebook [8192,512] f32
// Reference semantics replicated exactly:
//   p    = z @ cb.T                       (fp32 accum)
//   dist = fl( fl(r_m + c_n) - 2*p )      (fp32, ULP(~512) grid => ties!)
//   idx  = argmin dist, first index on ties
//   out  = concat( z + fl(q - z) [N*512], idx as f32 [N], 1.25*mean((z-q)^2) )
// ---------------------------------------------------------------------------

#define NTOK_MAX 32768
#define KCB_MAX  8192

__device__ unsigned long long g_bestkey[NTOK_MAX];
__device__ float              g_codenorm[KCB_MAX];   // ||e_n||^2
__device__ float              g_zn[NTOK_MAX];        // ||z_m||^2
__device__ float              g_tokensum[NTOK_MAX];

// ---- packed f32x2 helpers --------------------------------------------------
__device__ __forceinline__ unsigned long long dup2(float x) {
    unsigned long long d;
    asm("mov.b64 %0, {%1, %1};" : "=l"(d) : "f"(x));
    return d;
}
__device__ __forceinline__ void fma2(unsigned long long& acc,
                                     unsigned long long a,
                                     unsigned long long b) {
    asm("fma.rn.f32x2 %0, %1, %2, %0;" : "+l"(acc) : "l"(a), "l"(b));
}
__device__ __forceinline__ void unpack2(unsigned long long v, float& lo, float& hi) {
    asm("mov.b64 {%0, %1}, %2;" : "=f"(lo), "=f"(hi) : "l"(v));
}
// order-preserving float -> uint map (monotone increasing)
__device__ __forceinline__ unsigned ordf(float f) {
    unsigned u = __float_as_uint(f);
    return (u & 0x80000000u) ? ~u : (u | 0x80000000u);
}

// ---------------------------------------------------------------------------
__global__ void vq_init_kernel(int ntok) {
    int i = blockIdx.x * blockDim.x + threadIdx.x;
    if (i < ntok) g_bestkey[i] = 0ull;
}

// row norm ||v||^2 into a __device__ global selected by `dest`
// (device globals must NOT be passed as kernel args from host code).
__global__ void vq_rownorm_kernel(const float* __restrict__ X, int dest) {
    int c = blockIdx.x;
    int t = threadIdx.x;
    float4 v = reinterpret_cast<const float4*>(X + (size_t)c * 512)[t];
    float s = v.x * v.x + v.y * v.y + v.z * v.z + v.w * v.w;
    #pragma unroll
    for (int off = 16; off; off >>= 1)
        s += __shfl_xor_sync(0xFFFFFFFFu, s, off);
    __shared__ float ws[4];
    if ((t & 31) == 0) ws[t >> 5] = s;
    __syncthreads();
    if (t == 0) {
        float r = ws[0] + ws[1] + ws[2] + ws[3];
        if (dest == 0) g_codenorm[c] = r;
        else           g_zn[c] = r;
    }
}

// ---------------------------------------------------------------------------
// Fused fp32 GEMM (128x128 tile, BK=16, 256 threads, 8x8/thread via f32x2)
// + reference-exact dist rounding + argmin(first-index ties) publish.
// ---------------------------------------------------------------------------
#define BM 128
#define BN 128
#define BK 16
#define TS 132

__global__ __launch_bounds__(256, 2)
void vq_gemm_kernel(const float* __restrict__ Z, const float* __restrict__ CB,
                    int kcb) {
    __shared__ float As[2][BK * TS];
    __shared__ float Bs[2][BK * TS];

    const int tid = threadIdx.x;
    const int tx = tid & 15;
    const int ty = tid >> 4;
    const int mBase = blockIdx.y * BM;
    const int nBase = blockIdx.x * BN;

    const int lrow = tid >> 2;
    const int lcol = (tid & 3) << 2;

    const float* Ap = Z  + (size_t)(mBase + lrow) * 512 + lcol;
    const float* Bp = CB + (size_t)(nBase + lrow) * 512 + lcol;

    float4 ra0 = *reinterpret_cast<const float4*>(Ap);
    float4 ra1 = *reinterpret_cast<const float4*>(Ap + (size_t)64 * 512);
    float4 rb0 = *reinterpret_cast<const float4*>(Bp);
    float4 rb1 = *reinterpret_cast<const float4*>(Bp + (size_t)64 * 512);

    unsigned long long acc[8][4];
    #pragma unroll
    for (int i = 0; i < 8; ++i)
        #pragma unroll
        for (int j = 0; j < 4; ++j) acc[i][j] = 0ull;

    {
        float a0v[4] = {ra0.x, ra0.y, ra0.z, ra0.w};
        float a1v[4] = {ra1.x, ra1.y, ra1.z, ra1.w};
        float b0v[4] = {rb0.x, rb0.y, rb0.z, rb0.w};
        float b1v[4] = {rb1.x, rb1.y, rb1.z, rb1.w};
        #pragma unroll
        for (int j = 0; j < 4; ++j) {
            As[0][(lcol + j) * TS + lrow]      = a0v[j];
            As[0][(lcol + j) * TS + lrow + 64] = a1v[j];
            Bs[0][(lcol + j) * TS + lrow]      = b0v[j];
            Bs[0][(lcol + j) * TS + lrow + 64] = b1v[j];
        }
    }
    __syncthreads();

    int buf = 0;
    const int NK = 512 / BK;  // 32
    for (int t = 0; t < NK; ++t) {
        if (t + 1 < NK) {
            Ap += BK; Bp += BK;
            ra0 = *reinterpret_cast<const float4*>(Ap);
            ra1 = *reinterpret_cast<const float4*>(Ap + (size_t)64 * 512);
            rb0 = *reinterpret_cast<const float4*>(Bp);
            rb1 = *reinterpret_cast<const float4*>(Bp + (size_t)64 * 512);
        }

        #pragma unroll
        for (int k = 0; k < BK; ++k) {
            const float* ap = &As[buf][k * TS + ty * 8];
            float4 av0 = *reinterpret_cast<const float4*>(ap);
            float4 av1 = *reinterpret_cast<const float4*>(ap + 4);
            const float* bp_ = &Bs[buf][k * TS + tx * 8];
            ulonglong2 bv0 = *reinterpret_cast<const ulonglong2*>(bp_);
            ulonglong2 bv1 = *reinterpret_cast<const ulonglong2*>(bp_ + 4);
            unsigned long long bp[4] = {bv0.x, bv0.y, bv1.x, bv1.y};
            float af[8] = {av0.x, av0.y, av0.z, av0.w,
                           av1.x, av1.y, av1.z, av1.w};
            #pragma unroll
            for (int i = 0; i < 8; ++i) {
                unsigned long long da = dup2(af[i]);
                fma2(acc[i][0], da, bp[0]);
                fma2(acc[i][1], da, bp[1]);
                fma2(acc[i][2], da, bp[2]);
                fma2(acc[i][3], da, bp[3]);
            }
        }

        if (t + 1 < NK) {
            int nb = buf ^ 1;
            float a0v[4] = {ra0.x, ra0.y, ra0.z, ra0.w};
            float a1v[4] = {ra1.x, ra1.y, ra1.z, ra1.w};
            float b0v[4] = {rb0.x, rb0.y, rb0.z, rb0.w};
            float b1v[4] = {rb1.x, rb1.y, rb1.z, rb1.w};
            #pragma unroll
            for (int j = 0; j < 4; ++j) {
                As[nb][(lcol + j) * TS + lrow]      = a0v[j];
                As[nb][(lcol + j) * TS + lrow + 64] = a1v[j];
                Bs[nb][(lcol + j) * TS + lrow]      = b0v[j];
                Bs[nb][(lcol + j) * TS + lrow + 64] = b1v[j];
            }
        }
        __syncthreads();
        buf ^= 1;
    }

    // ---- epilogue: reference-exact dist rounding, argmin, publish ---------
    float cn[8];
    #pragma unroll
    for (int j = 0; j < 8; ++j) cn[j] = g_codenorm[nBase + tx * 8 + j];

    #pragma unroll
    for (int i = 0; i < 8; ++i) {
        const float r = g_zn[mBase + ty * 8 + i];
        unsigned long long bestKey = 0ull;
        #pragma unroll
        for (int j = 0; j < 4; ++j) {
            float p0, p1;
            unpack2(acc[i][j], p0, p1);
            int n0 = nBase + tx * 8 + j * 2;
            // dist = fl( fl(r + c) - 2*p )   (2*p exact; fma = single rounding)
            float S0 = __fadd_rn(r, cn[j * 2]);
            float S1 = __fadd_rn(r, cn[j * 2 + 1]);
            float d0 = __fmaf_rn(-2.0f, p0, S0);
            float d1 = __fmaf_rn(-2.0f, p1, S1);
            // min dist; tie -> smallest index  (maximize packed key)
            unsigned long long k0 =
                ((unsigned long long)(~ordf(d0)) << 32) | (unsigned)(kcb - 1 - n0);
            unsigned long long k1 =
                ((unsigned long long)(~ordf(d1)) << 32) | (unsigned)(kcb - 2 - n0);
            if (k0 > bestKey) bestKey = k0;
            if (k1 > bestKey) bestKey = k1;
        }
        #pragma unroll
        for (int off = 8; off; off >>= 1) {
            unsigned long long o = __shfl_xor_sync(0xFFFFFFFFu, bestKey, off);
            if (o > bestKey) bestKey = o;
        }
        if (tx == 0)
            atomicMax(&g_bestkey[mBase + ty * 8 + i], bestKey);
    }
}

// ---------------------------------------------------------------------------
// Gather winner; write quantized_st = z + fl(q - z) (reference-exact),
// index as f32, per-token squared error for the loss.
// ---------------------------------------------------------------------------
__global__ void vq_quantize_kernel(const float* __restrict__ Z,
                                   const float* __restrict__ CB,
                                   float* __restrict__ out,
                                   int kcb, int writeIdx, size_t idxOff) {
    int t = blockIdx.x;
    int tid = threadIdx.x;
    unsigned long long key = g_bestkey[t];
    int n = (kcb - 1) - (int)(unsigned)(key & 0xFFFFFFFFull);

    float4 q = reinterpret_cast<const float4*>(CB + (size_t)n * 512)[tid];
    float4 z = reinterpret_cast<const float4*>(Z + (size_t)t * 512)[tid];

    // straight-through value, elementwise fp32 exactly as reference
    float4 o;
    float dx = __fsub_rn(q.x, z.x);
    float dy = __fsub_rn(q.y, z.y);
    float dz = __fsub_rn(q.z, z.z);
    float dw = __fsub_rn(q.w, z.w);
    o.x = __fadd_rn(z.x, dx);
    o.y = __fadd_rn(z.y, dy);
    o.z = __fadd_rn(z.z, dz);
    o.w = __fadd_rn(z.w, dw);
    reinterpret_cast<float4*>(out)[(size_t)t * 128 + tid] = o;

    float s = dx * dx + dy * dy + dz * dz + dw * dw;
    #pragma unroll
    for (int off = 16; off; off >>= 1)
        s += __shfl_xor_sync(0xFFFFFFFFu, s, off);
    __shared__ float ws[4];
    if ((tid & 31) == 0) ws[tid >> 5] = s;
    __syncthreads();
    if (tid == 0) {
        g_tokensum[t] = ws[0] + ws[1] + ws[2] + ws[3];
        if (writeIdx) out[idxOff + t] = (float)n;
    }
}

// Deterministic loss reduction (no float atomics -> replay-identical output).
__global__ void vq_loss_kernel(float* __restrict__ out, size_t lossOff, int ntok) {
    __shared__ float sm[1024];
    int i = threadIdx.x;
    float s = 0.0f;
    for (int j = i; j < ntok; j += 1024) s += g_tokensum[j];
    sm[i] = s;
    __syncthreads();
    for (int st = 512; st; st >>= 1) {
        if (i < st) sm[i] += sm[i + st];
        __syncthreads();
    }
    if (i == 0)
        out[lossOff] = 1.25f * sm[0] / ((float)ntok * 512.0f);
}

// ---------------------------------------------------------------------------
extern "C" void kernel_launch(void* const* d_in, const int* in_sizes, int n_in,
                              void* d_out, int out_size) {
    const float* p0 = (const float*)d_in[0];
    const float* p1 = (const float*)d_in[1];
    int s0 = in_sizes[0], s1 = in_sizes[1];

    const float* Z  = p0;
    const float* CB = p1;
    int zN = s0, cN = s1;
    if (s1 > s0) { Z = p1; CB = p0; zN = s1; cN = s0; }

    const int ntok = zN / 512;   // 32768
    const int kcb  = cN / 512;   // 8192
    float* out = (float*)d_out;

    const size_t qElems = (size_t)ntok * 512;
    const int writeIdx  = ((size_t)out_size >= qElems + (size_t)ntok);
    const int writeLoss = ((size_t)out_size >= qElems + (size_t)ntok + 1);

    vq_init_kernel<<<(ntok + 1023) / 1024, 1024>>>(ntok);
    vq_rownorm_kernel<<<kcb, 128>>>(CB, 0);   // -> g_codenorm
    vq_rownorm_kernel<<<ntok, 128>>>(Z, 1);   // -> g_zn

    dim3 grid(kcb / BN, ntok / BM);  // (64, 256)
    vq_gemm_kernel<<<grid, 256>>>(Z, CB, kcb);

    vq_quantize_kernel<<<ntok, 128>>>(Z, CB, out, kcb, writeIdx, qElems);
    if (writeLoss)
        vq_loss_kernel<<<1, 1024>>>(out, qElems + (size_t)ntok, ntok);
}